// round 8
// baseline (speedup 1.0000x reference)
#include <cuda_runtime.h>
#include <cuda_bf16.h>

#define EPS 1e-5f

// Scratch (device globals: allocation-free)
__device__ float g_a[256 * 32];     // a = x@W1 + b1
__device__ float g_s[256];          // row sums of a
__device__ float g_q[256];          // row sums of a^2
__device__ float g_U[256 * 1024];   // U[i, o*32+e] = sum_d a[i,d]*gamma[d*32+e]*W2[(d*32+e)*32+o]
__device__ float g_c[32];           // c[o] = sum_k gamma[k]*W2[k,o]
__device__ float g_t[32];           // t[o] = sum_k beta[k]*W2[k,o] + b2[o]

// ---- f32x2 packed helpers (Blackwell) ----
#define FMA_F32X2(acc, a, b) \
    asm("fma.rn.f32x2 %0, %1, %2, %3;" : "=l"(acc) : "l"(a), "l"(b), "l"(acc))
#define PACK2(out, lo, hi) \
    asm("mov.b64 %0, {%1, %2};" : "=l"(out) : "f"(lo), "f"(hi))
#define DUP2(out, v) \
    asm("mov.b64 %0, {%1, %1};" : "=l"(out) : "f"(v))
#define UNPACK2(lo, hi, in) \
    asm("mov.b64 {%0, %1}, %2;" : "=f"(lo), "=f"(hi) : "l"(in))

// Kernel A (fused): blocks 0..127: it = bx>>2 (8-row i-tile), ct = bx&3 (256-col
// U tile). Block 128 computes c,t.  U stored TRANSPOSED: col index = o*32+e.
__global__ __launch_bounds__(256) void kA(const float* __restrict__ x,
                                          const float* __restrict__ W1,
                                          const float* __restrict__ b1,
                                          const float* __restrict__ gamma,
                                          const float* __restrict__ beta,
                                          const float* __restrict__ W2,
                                          const float* __restrict__ b2) {
    int bx = blockIdx.x;
    int tid = threadIdx.x;

    if (bx == 128) {
        __shared__ float rc[8][32], rt[8][32];
        int o = tid & 31, grp = tid >> 5;
        float pc = 0.f, pt = 0.f;
        int k0 = grp * 128;
#pragma unroll 8
        for (int k = k0; k < k0 + 128; k++) {
            float w = W2[k * 32 + o];
            pc += gamma[k] * w;
            pt += beta[k] * w;
        }
        rc[grp][o] = pc;
        rt[grp][o] = pt;
        __syncthreads();
        if (tid < 32) {
            float cc = 0.f, tt = b2[o];
#pragma unroll
            for (int g = 0; g < 8; g++) { cc += rc[g][o]; tt += rt[g][o]; }
            g_c[o] = cc;
            g_t[o] = tt;
        }
        return;
    }

    int it = bx >> 2, ct = bx & 3;
    int i0 = it * 8;

    __shared__ __align__(16) float xs[8 * 256];   // 8 KB x tile
    __shared__ float red[8][8][32];               // 8 KB partials
    __shared__ float as_[8][32];

    {
        const float4* xp = (const float4*)(x + i0 * 256);
        float4* sp = (float4*)xs;
        sp[tid]       = xp[tid];
        sp[tid + 256] = xp[tid + 256];
    }
    __syncthreads();

    int h = tid & 31, grp = tid >> 5;
    {
        float acc[8];
#pragma unroll
        for (int r = 0; r < 8; r++) acc[r] = 0.f;
#pragma unroll
        for (int cc = 0; cc < 8; cc++) {
            int c = grp * 32 + cc * 4;
            float w0 = W1[(c + 0) * 32 + h];
            float w1 = W1[(c + 1) * 32 + h];
            float w2 = W1[(c + 2) * 32 + h];
            float w3 = W1[(c + 3) * 32 + h];
#pragma unroll
            for (int r = 0; r < 8; r++) {
                float4 xv = *(const float4*)&xs[r * 256 + c];
                acc[r] += xv.x * w0 + xv.y * w1 + xv.z * w2 + xv.w * w3;
            }
        }
#pragma unroll
        for (int r = 0; r < 8; r++) red[grp][r][h] = acc[r];
    }
    __syncthreads();

    {
        int r = tid >> 5;
        float a = b1[h];
#pragma unroll
        for (int g = 0; g < 8; g++) a += red[g][r][h];
        as_[r][h] = a;
        if (ct == 0) g_a[(i0 + r) * 32 + h] = a;
        float s = a, q = a * a;
#pragma unroll
        for (int off = 16; off; off >>= 1) {
            s += __shfl_down_sync(0xffffffffu, s, off);
            q += __shfl_down_sync(0xffffffffu, q, off);
        }
        if (ct == 0 && h == 0) { g_s[i0 + r] = s; g_q[i0 + r] = q; }
    }
    __syncthreads();

    // U columns, transposed layout: col = o*32 + e
    {
        int col = ct * 256 + tid;
        int o = col >> 5, e = col & 31;
        float g[32];
#pragma unroll
        for (int d = 0; d < 32; d++)
            g[d] = gamma[d * 32 + e] * W2[(d * 32 + e) * 32 + o];
#pragma unroll
        for (int r = 0; r < 8; r++) {
            float acc2 = 0.f;
#pragma unroll
            for (int d = 0; d < 32; d++) acc2 += as_[r][d] * g[d];
            g_U[(i0 + r) * 1024 + col] = acc2;
        }
    }
}

// Kernel 3: out[i,j,o] = r_ij * (sum_e U[i,e,o]*a[j,e] - mu_ij*c[o]) + t[o]
// Block: i-tile 8 x j-tile 16, 128 threads = 32 o x 4 jgrp; thread owns 4 j
// packed into 2 f32x2 lanes. U rows [ii][o][e] in smem padded to 36 floats.
#define UPITCH 36
__global__ __launch_bounds__(128) void k3_out(float* __restrict__ out) {
    __shared__ __align__(16) float Us[8 * 32 * UPITCH];  // 36 KB
    __shared__ __align__(16) float ajs[16 * 32];         // 2 KB
    __shared__ float ss[8], qs[8];

    int tid = threadIdx.x;
    int j0 = blockIdx.x * 16, i0 = blockIdx.y * 8;

    // Load U tile (8 KF) from gmem [i][o*32+e] into padded smem [ii][o][e]
    {
        const float4* up = (const float4*)(g_U + i0 * 1024);
#pragma unroll
        for (int k = 0; k < 16; k++) {
            int gi = tid + k * 128;          // float4 index in [0,2048)
            float4 v = up[gi];
            int ii = gi >> 8;                // 256 float4 per i-row
            int rem = gi & 255;
            int o = rem >> 3, e4 = rem & 7;
            *(float4*)&Us[ii * (32 * UPITCH) + o * UPITCH + e4 * 4] = v;
        }
        ((float4*)ajs)[tid] = ((const float4*)(g_a + j0 * 32))[tid];
        if (tid < 8) { ss[tid] = g_s[i0 + tid]; qs[tid] = g_q[i0 + tid]; }
    }
    __syncthreads();

    int o = tid & 31, jgrp = tid >> 5;

    // aj for 4 j, packed into f32x2 pairs: ajp[p][e] = (aj[2p][e], aj[2p+1][e])
    unsigned long long ajp[2][32];
#pragma unroll
    for (int p = 0; p < 2; p++) {
        const float* r0 = &ajs[(jgrp * 4 + 2 * p + 0) * 32];
        const float* r1 = &ajs[(jgrp * 4 + 2 * p + 1) * 32];
#pragma unroll
        for (int e4 = 0; e4 < 8; e4++) {
            float4 a0 = *(const float4*)&r0[e4 * 4];
            float4 a1 = *(const float4*)&r1[e4 * 4];
            PACK2(ajp[p][e4 * 4 + 0], a0.x, a1.x);
            PACK2(ajp[p][e4 * 4 + 1], a0.y, a1.y);
            PACK2(ajp[p][e4 * 4 + 2], a0.z, a1.z);
            PACK2(ajp[p][e4 * 4 + 3], a0.w, a1.w);
        }
    }

    float sj[4], qj[4];
#pragma unroll
    for (int k = 0; k < 4; k++) {
        int j = j0 + jgrp * 4 + k;
        sj[k] = g_s[j];
        qj[k] = g_q[j];
    }
    float co = g_c[o], to = g_t[o];
    const float inv = 1.0f / 1024.0f;

    for (int ii = 0; ii < 8; ii++) {
        const float* urow = &Us[ii * (32 * UPITCH) + o * UPITCH];
        float u[32];
#pragma unroll
        for (int e4 = 0; e4 < 8; e4++) {
            float4 v = *(const float4*)&urow[e4 * 4];
            u[e4 * 4 + 0] = v.x;
            u[e4 * 4 + 1] = v.y;
            u[e4 * 4 + 2] = v.z;
            u[e4 * 4 + 3] = v.w;
        }
        unsigned long long acc0 = 0ull, acc1 = 0ull;
#pragma unroll
        for (int e = 0; e < 32; e++) {
            unsigned long long uu;
            DUP2(uu, u[e]);
            FMA_F32X2(acc0, uu, ajp[0][e]);
            FMA_F32X2(acc1, uu, ajp[1][e]);
        }
        float accv[4];
        UNPACK2(accv[0], accv[1], acc0);
        UNPACK2(accv[2], accv[3], acc1);

        float si = ss[ii], qi = qs[ii];
        size_t base = ((size_t)(i0 + ii) * 256 + j0 + jgrp * 4) * 32 + o;
#pragma unroll
        for (int k = 0; k < 4; k++) {
            float mu = si * sj[k] * inv;
            float var = qi * qj[k] * inv - mu * mu;
            float r = rsqrtf(var + EPS);
            out[base + (size_t)k * 32] = r * (accv[k] - mu * co) + to;
        }
    }
}

extern "C" void kernel_launch(void* const* d_in, const int* in_sizes, int n_in,
                              void* d_out, int out_size) {
    const float* x     = (const float*)d_in[0];
    const float* W1    = (const float*)d_in[1];
    const float* b1    = (const float*)d_in[2];
    const float* gamma = (const float*)d_in[3];
    const float* beta  = (const float*)d_in[4];
    const float* W2    = (const float*)d_in[5];
    const float* b2    = (const float*)d_in[6];
    float* out = (float*)d_out;

    kA<<<129, 256>>>(x, W1, b1, gamma, beta, W2, b2);
    k3_out<<<dim3(16, 32), 128>>>(out);
}

// round 9
// speedup vs baseline: 1.0200x; 1.0200x over previous
#include <cuda_runtime.h>
#include <cuda_bf16.h>

#define EPS 1e-5f

// Scratch (device globals: allocation-free)
__device__ float g_a[256 * 32];     // a = x@W1 + b1
__device__ float g_s[256];          // row sums of a
__device__ float g_q[256];          // row sums of a^2
__device__ float g_U[256 * 1024];   // U[i, o*32+e] = sum_d a[i,d]*gamma[d*32+e]*W2[(d*32+e)*32+o]
__device__ float g_c[32];           // c[o] = sum_k gamma[k]*W2[k,o]
__device__ float g_t[32];           // t[o] = sum_k beta[k]*W2[k,o] + b2[o]

// ---- f32x2 packed helpers (Blackwell) ----
#define FMA_F32X2(acc, a, b) \
    asm("fma.rn.f32x2 %0, %1, %2, %3;" : "=l"(acc) : "l"(a), "l"(b), "l"(acc))
#define PACK2(out, lo, hi) \
    asm("mov.b64 %0, {%1, %2};" : "=l"(out) : "f"(lo), "f"(hi))
#define DUP2(out, v) \
    asm("mov.b64 %0, {%1, %1};" : "=l"(out) : "f"(v))
#define UNPACK2(lo, hi, in) \
    asm("mov.b64 {%0, %1}, %2;" : "=f"(lo), "=f"(hi) : "l"(in))

// Kernel A (fused): blocks 0..127: it = bx>>2 (8-row i-tile), ct = bx&3 (256-col
// U tile). Block 128 computes c,t.  U stored TRANSPOSED: col index = o*32+e.
__global__ __launch_bounds__(256) void kA(const float* __restrict__ x,
                                          const float* __restrict__ W1,
                                          const float* __restrict__ b1,
                                          const float* __restrict__ gamma,
                                          const float* __restrict__ beta,
                                          const float* __restrict__ W2,
                                          const float* __restrict__ b2) {
    int bx = blockIdx.x;
    int tid = threadIdx.x;

    if (bx == 128) {
        __shared__ float rc[8][32], rt[8][32];
        int o = tid & 31, grp = tid >> 5;
        float pc = 0.f, pt = 0.f;
        int k0 = grp * 128;
#pragma unroll 8
        for (int k = k0; k < k0 + 128; k++) {
            float w = W2[k * 32 + o];
            pc += gamma[k] * w;
            pt += beta[k] * w;
        }
        rc[grp][o] = pc;
        rt[grp][o] = pt;
        __syncthreads();
        if (tid < 32) {
            float cc = 0.f, tt = b2[o];
#pragma unroll
            for (int g = 0; g < 8; g++) { cc += rc[g][o]; tt += rt[g][o]; }
            g_c[o] = cc;
            g_t[o] = tt;
        }
        return;
    }

    int it = bx >> 2, ct = bx & 3;
    int i0 = it * 8;

    __shared__ __align__(16) float xs[8 * 256];   // 8 KB x tile
    __shared__ float red[8][8][32];               // 8 KB partials
    __shared__ float as_[8][32];

    {
        const float4* xp = (const float4*)(x + i0 * 256);
        float4* sp = (float4*)xs;
        sp[tid]       = xp[tid];
        sp[tid + 256] = xp[tid + 256];
    }
    __syncthreads();

    int h = tid & 31, grp = tid >> 5;
    {
        float acc[8];
#pragma unroll
        for (int r = 0; r < 8; r++) acc[r] = 0.f;
#pragma unroll
        for (int cc = 0; cc < 8; cc++) {
            int c = grp * 32 + cc * 4;
            float w0 = W1[(c + 0) * 32 + h];
            float w1 = W1[(c + 1) * 32 + h];
            float w2 = W1[(c + 2) * 32 + h];
            float w3 = W1[(c + 3) * 32 + h];
#pragma unroll
            for (int r = 0; r < 8; r++) {
                float4 xv = *(const float4*)&xs[r * 256 + c];
                acc[r] += xv.x * w0 + xv.y * w1 + xv.z * w2 + xv.w * w3;
            }
        }
#pragma unroll
        for (int r = 0; r < 8; r++) red[grp][r][h] = acc[r];
    }
    __syncthreads();

    {
        int r = tid >> 5;
        float a = b1[h];
#pragma unroll
        for (int g = 0; g < 8; g++) a += red[g][r][h];
        as_[r][h] = a;
        if (ct == 0) g_a[(i0 + r) * 32 + h] = a;
        float s = a, q = a * a;
#pragma unroll
        for (int off = 16; off; off >>= 1) {
            s += __shfl_down_sync(0xffffffffu, s, off);
            q += __shfl_down_sync(0xffffffffu, q, off);
        }
        if (ct == 0 && h == 0) { g_s[i0 + r] = s; g_q[i0 + r] = q; }
    }
    __syncthreads();

    // U columns, transposed layout: col = o*32 + e
    {
        int col = ct * 256 + tid;
        int o = col >> 5, e = col & 31;
        float g[32];
#pragma unroll
        for (int d = 0; d < 32; d++)
            g[d] = gamma[d * 32 + e] * W2[(d * 32 + e) * 32 + o];
#pragma unroll
        for (int r = 0; r < 8; r++) {
            float acc2 = 0.f;
#pragma unroll
            for (int d = 0; d < 32; d++) acc2 += as_[r][d] * g[d];
            g_U[(i0 + r) * 1024 + col] = acc2;
        }
    }
}

// Kernel 3: out[i,j,o] = r_ij * (sum_e U[i,e,o]*a[j,e] - mu_ij*c[o]) + t[o]
// Block: i-tile 8, j-chunk 32 (16 packed pairs). 128 threads = 32 o x 4 slots;
// each thread owns 2 i rows (u dup'd from gmem) and loops all 16 j-pairs ->
// acc[2][16] = 32 independent FFMA2 chains. aj pairs pre-packed in smem,
// consumed via broadcast LDS.128. LN factors precomputed into a PQ table.
__global__ __launch_bounds__(128) void k3_out(float* __restrict__ out) {
    __shared__ __align__(16) unsigned long long ajp_s[16][32]; // (a[j0+2jp][e], a[j0+2jp+1][e])
    __shared__ __align__(16) float pq_s[8][16][4];             // P0,P1,Q0,Q1 per (iloc, jp)

    int tid = threadIdx.x;
    int o = tid & 31, slot = tid >> 5;
    int j0 = blockIdx.x * 32, i0 = blockIdx.y * 8;

    // Prologue 1: pack aj pairs (512 u64 entries)
#pragma unroll
    for (int k = 0; k < 4; k++) {
        int idx = tid + k * 128;
        int jp = idx >> 5, e = idx & 31;
        float a0 = g_a[(j0 + 2 * jp) * 32 + e];
        float a1 = g_a[(j0 + 2 * jp + 1) * 32 + e];
        unsigned long long v;
        PACK2(v, a0, a1);
        ajp_s[jp][e] = v;
    }
    // Prologue 2: PQ table, one (iloc, jp) entry per thread
    {
        int iloc = tid >> 4, jp = tid & 15;
        const float inv = 1.0f / 1024.0f;
        float si = g_s[i0 + iloc] * inv;
        float qi = g_q[i0 + iloc] * inv;
        float P[2], Q[2];
#pragma unroll
        for (int h = 0; h < 2; h++) {
            int j = j0 + 2 * jp + h;
            float sj = g_s[j], qj = g_q[j];
            float mu = si * sj;
            float var = qi * qj - mu * mu;
            float r = rsqrtf(var + EPS);
            P[h] = r;
            Q[h] = r * mu;
        }
        *(float4*)&pq_s[iloc][jp][0] = make_float4(P[0], P[1], Q[0], Q[1]);
    }
    __syncthreads();

    float co = g_c[o], to = g_t[o];

    unsigned long long acc[2][16];
#pragma unroll
    for (int i2 = 0; i2 < 2; i2++)
#pragma unroll
        for (int jp = 0; jp < 16; jp++) acc[i2][jp] = 0ull;

    const float* ubase = g_U + (size_t)(i0 + slot * 2) * 1024 + o * 32;

#pragma unroll 1
    for (int ec = 0; ec < 4; ec++) {
        unsigned long long ud[2][8];
#pragma unroll
        for (int i2 = 0; i2 < 2; i2++) {
            float4 v0 = *(const float4*)(ubase + i2 * 1024 + ec * 8);
            float4 v1 = *(const float4*)(ubase + i2 * 1024 + ec * 8 + 4);
            DUP2(ud[i2][0], v0.x); DUP2(ud[i2][1], v0.y);
            DUP2(ud[i2][2], v0.z); DUP2(ud[i2][3], v0.w);
            DUP2(ud[i2][4], v1.x); DUP2(ud[i2][5], v1.y);
            DUP2(ud[i2][6], v1.z); DUP2(ud[i2][7], v1.w);
        }
#pragma unroll
        for (int jp = 0; jp < 16; jp++) {
            const ulonglong2* bp = (const ulonglong2*)&ajp_s[jp][ec * 8];
            ulonglong2 b01 = bp[0], b23 = bp[1], b45 = bp[2], b67 = bp[3];
            unsigned long long b[8] = {b01.x, b01.y, b23.x, b23.y,
                                       b45.x, b45.y, b67.x, b67.y};
#pragma unroll
            for (int e = 0; e < 8; e++) {
                FMA_F32X2(acc[0][jp], ud[0][e], b[e]);
                FMA_F32X2(acc[1][jp], ud[1][e], b[e]);
            }
        }
    }

    // Epilogue: out = P*acc + (to - Q*co), 64 outputs/thread, o-coalesced stores
#pragma unroll
    for (int i2 = 0; i2 < 2; i2++) {
        int i = i0 + slot * 2 + i2;
        int iloc = slot * 2 + i2;
        float* op = out + ((size_t)i * 256 + j0) * 32 + o;
#pragma unroll
        for (int jp = 0; jp < 16; jp++) {
            float4 pq = *(const float4*)&pq_s[iloc][jp][0];  // broadcast LDS.128
            float a0, a1;
            UNPACK2(a0, a1, acc[i2][jp]);
            float r0 = pq.x * a0 + (to - pq.z * co);
            float r1 = pq.y * a1 + (to - pq.w * co);
            op[(size_t)(2 * jp) * 32] = r0;
            op[(size_t)(2 * jp + 1) * 32] = r1;
        }
    }
}

extern "C" void kernel_launch(void* const* d_in, const int* in_sizes, int n_in,
                              void* d_out, int out_size) {
    const float* x     = (const float*)d_in[0];
    const float* W1    = (const float*)d_in[1];
    const float* b1    = (const float*)d_in[2];
    const float* gamma = (const float*)d_in[3];
    const float* beta  = (const float*)d_in[4];
    const float* W2    = (const float*)d_in[5];
    const float* b2    = (const float*)d_in[6];
    float* out = (float*)d_out;

    kA<<<129, 256>>>(x, W1, b1, gamma, beta, W2, b2);
    k3_out<<<dim3(8, 32), 128>>>(out);
}